// round 9
// baseline (speedup 1.0000x reference)
#include <cuda_runtime.h>
#include <math.h>

// Shapes fixed by reference: [2,4,32,64,64]
constexpr int Cc    = 32;          // channels
constexpr int HW    = 4096;        // 64*64 positions
constexpr int NI    = 8;           // B*L items
constexpr int BPI   = 64;          // blocks per item (2 subtiles of 32 positions)
constexpr int TP    = 32;          // positions per subtile
constexpr int PITCH = 36;          // 9 x 16B rows: LDS.128-aligned, odd quad-bank stride
constexpr int TH1   = 192;         // 3 groups x 64 threads
constexpr int NBLK  = BPI * NI;    // 512 total blocks

// Single accumulator: [item][mat][32*32]. Zero at module load; the fused
// epilogue re-zeroes it after reading, so every graph replay starts clean.
__device__ float    g_acc[(size_t)NI * 3 * 1024];
__device__ unsigned g_ticket;      // zero-init; reset by the epilogue block

// Physical row for logical channel c: spreads the 8-strided row sets used by
// the main loop across all 8 quad-banks (conflict-free LDS.128).
__device__ __forceinline__ int rowmap(int c) { return ((c & 3) << 3) | (c >> 2); }

__global__ __launch_bounds__(TH1) void k_fused(const float* __restrict__ S,
                                               const float* __restrict__ T,
                                               float* __restrict__ out) {
    __shared__ __align__(16) float sS[2][Cc * PITCH];
    __shared__ __align__(16) float sT[2][Cc * PITCH];
    __shared__ __align__(16) float ivS[2][TP];
    __shared__ __align__(16) float ivT[2][TP];
    __shared__ __align__(16) float wgt[2][3 * TP];   // wA | wB | wM per subtile
    __shared__ unsigned s_last;

    const int n   = blockIdx.y;
    const int blk = blockIdx.x;
    const int tid = threadIdx.x;

    const float4* __restrict__ Sb4 = (const float4*)(S + (size_t)n * Cc * HW);
    const float4* __restrict__ Tb4 = (const float4*)(T + (size_t)n * Cc * HW);

    // Per-thread load slots: 256 float4-pairs per subtile; slots tid, tid+192
    const int p0 = blk * 2 * TP;
    const int c0 = tid >> 3,          q0 = tid & 7;
    const int v1 = tid + TH1;
    const int c1 = (v1 < 256) ? (v1 >> 3) : 0, q1 = (v1 < 256) ? (v1 & 7) : 0;
    const bool has1 = (v1 < 256);

    // ---- Prefetch subtile 0 ----
    float4 a0 = Sb4[(size_t)c0 * (HW / 4) + (p0 >> 2) + q0];
    float4 b0 = Tb4[(size_t)c0 * (HW / 4) + (p0 >> 2) + q0];
    float4 a1 = {}, b1 = {};
    if (has1) {
        a1 = Sb4[(size_t)c1 * (HW / 4) + (p0 >> 2) + q1];
        b1 = Tb4[(size_t)c1 * (HW / 4) + (p0 >> 2) + q1];
    }

    const int grp = tid >> 6;          // 0:A(T.T^t) 1:B(S.S^t) 2:M(S.T^t)
    const int lt  = tid & 63;
    const int ii  = lt >> 3;           // 0..7
    const int jj  = lt & 7;            // 0..7

    unsigned long long acc2[16];
#pragma unroll
    for (int k = 0; k < 16; ++k) acc2[k] = 0ull;

#pragma unroll
    for (int t = 0; t < 2; ++t) {
        // ---- Store current subtile to smem (row-permuted) ----
        *(float4*)&sS[t][rowmap(c0) * PITCH + 4 * q0] = a0;
        *(float4*)&sT[t][rowmap(c0) * PITCH + 4 * q0] = b0;
        if (has1) {
            *(float4*)&sS[t][rowmap(c1) * PITCH + 4 * q1] = a1;
            *(float4*)&sT[t][rowmap(c1) * PITCH + 4 * q1] = b1;
        }

        if (t == 0) {   // prefetch subtile 1 while subtile 0 is processed
            const int pn = p0 + TP;
            a0 = Sb4[(size_t)c0 * (HW / 4) + (pn >> 2) + q0];
            b0 = Tb4[(size_t)c0 * (HW / 4) + (pn >> 2) + q0];
            if (has1) {
                a1 = Sb4[(size_t)c1 * (HW / 4) + (pn >> 2) + q1];
                b1 = Tb4[(size_t)c1 * (HW / 4) + (pn >> 2) + q1];
            }
        }
        __syncthreads();

        // ---- Norms: warp0 -> ivS, warp1 -> ivT (parallel chains) ----
        if (tid < TP) {
            const int p = tid;
            float ss = 0.f;
#pragma unroll
            for (int r = 0; r < Cc; ++r) { const float v = sS[t][r * PITCH + p]; ss = fmaf(v, v, ss); }
            ivS[t][p] = 1.f / (sqrtf(ss) + 1e-8f);
        } else if (tid < 2 * TP) {
            const int p = tid - TP;
            float st = 0.f;
#pragma unroll
            for (int r = 0; r < Cc; ++r) { const float v = sT[t][r * PITCH + p]; st = fmaf(v, v, st); }
            ivT[t][p] = 1.f / (sqrtf(st) + 1e-8f);
        }
        __syncthreads();
        if (tid < TP) {
            const float s = ivS[t][tid], w = ivT[t][tid];
            wgt[t][0 * TP + tid] = w * w;
            wgt[t][1 * TP + tid] = s * s;
            wgt[t][2 * TP + tid] = s * w;
        }
        __syncthreads();

        // ---- Gram accumulation (weights folded into xi) ----
        const float* __restrict__ Xi = (grp == 0) ? sT[t] : sS[t];
        const float* __restrict__ Xj = (grp == 1) ? sS[t] : sT[t];
        const float* xiB = Xi + ii * PITCH;
        const float* xjB = Xj + jj * PITCH;
        const float* wB  = wgt[t] + grp * TP;

#pragma unroll
        for (int p = 0; p < TP; p += 4) {
            const float4 w4 = *(const float4*)&wB[p];          // broadcast
            const unsigned long long wL = *(const unsigned long long*)&w4.x;
            const unsigned long long wH = *(const unsigned long long*)&w4.z;

            float4 xi4[4], xj4[4];
#pragma unroll
            for (int rr = 0; rr < 4; ++rr) xi4[rr] = *(const float4*)&xiB[(8 * rr) * PITCH + p];
#pragma unroll
            for (int qq = 0; qq < 4; ++qq) xj4[qq] = *(const float4*)&xjB[(8 * qq) * PITCH + p];

            unsigned long long xiL[4], xiH[4];
#pragma unroll
            for (int rr = 0; rr < 4; ++rr) {
                unsigned long long x = *(const unsigned long long*)&xi4[rr].x;
                unsigned long long y = *(const unsigned long long*)&xi4[rr].z;
                asm("mul.rn.f32x2 %0, %0, %1;" : "+l"(x) : "l"(wL));
                asm("mul.rn.f32x2 %0, %0, %1;" : "+l"(y) : "l"(wH));
                xiL[rr] = x; xiH[rr] = y;
            }
#pragma unroll
            for (int rr = 0; rr < 4; ++rr) {
#pragma unroll
                for (int qq = 0; qq < 4; ++qq) {
                    const unsigned long long xjL = *(const unsigned long long*)&xj4[qq].x;
                    const unsigned long long xjH = *(const unsigned long long*)&xj4[qq].z;
                    asm("fma.rn.f32x2 %0, %1, %2, %0;"
                        : "+l"(acc2[rr * 4 + qq]) : "l"(xiL[rr]), "l"(xjL));
                    asm("fma.rn.f32x2 %0, %1, %2, %0;"
                        : "+l"(acc2[rr * 4 + qq]) : "l"(xiH[rr]), "l"(xjH));
                }
            }
        }
        // No barrier needed: next iteration's STS targets the other buffer.
    }

    // ---- Fire-and-forget accumulation ----
    float* dst = g_acc + ((size_t)n * 3 + grp) * 1024;
#pragma unroll
    for (int rr = 0; rr < 4; ++rr)
#pragma unroll
        for (int qq = 0; qq < 4; ++qq) {
            const float2 v = *(const float2*)&acc2[rr * 4 + qq];
            atomicAdd(&dst[(4 * ii + rr) * 32 + 4 * jj + qq], v.x + v.y);
        }

    // ---- Ticket: last block runs the epilogue ----
    __threadfence();
    if (tid == 0) s_last = (atomicAdd(&g_ticket, 1u) == NBLK - 1);
    __syncthreads();
    if (!s_last) return;
    __threadfence();

    // Epilogue (one block, 192 threads): read 24576 sums from L2, weight,
    // square, reduce, write loss; re-zero accumulators + ticket for next replay.
    float local = 0.f;
    for (int e = tid; e < NI * 3 * 1024; e += TH1) {
        const float v = __ldcg(&g_acc[e]);
        const int mat = (e >> 10) % 3;
        local = fmaf((mat == 2) ? -2.f * v : v, v, local);
        g_acc[e] = 0.f;
    }
#pragma unroll
    for (int off = 16; off > 0; off >>= 1)
        local += __shfl_down_sync(0xffffffffu, local, off);

    __shared__ float wsum[6];
    if ((tid & 31) == 0) wsum[tid >> 5] = local;
    __syncthreads();
    if (tid == 0) {
        float s = wsum[0] + wsum[1] + wsum[2] + wsum[3] + wsum[4] + wsum[5];
        // loss = total / (HW^2) / (B*L)
        out[0] = s * (1.f / (16777216.f * 8.f));
        g_ticket = 0u;
    }
}

extern "C" void kernel_launch(void* const* d_in, const int* in_sizes, int n_in,
                              void* d_out, int out_size) {
    const float* S = (const float*)d_in[0];
    const float* T = (const float*)d_in[1];
    (void)in_sizes; (void)n_in; (void)out_size;

    dim3 g1(BPI, NI);
    k_fused<<<g1, TH1>>>(S, T, (float*)d_out);
}

// round 10
// speedup vs baseline: 1.9659x; 1.9659x over previous
#include <cuda_runtime.h>
#include <math.h>

// Shapes fixed by reference: [2,4,32,64,64]
constexpr int Cc    = 32;          // channels
constexpr int HW    = 4096;        // 64*64 positions
constexpr int NI    = 8;           // B*L items
constexpr int BPI   = 64;          // blocks per item (2 subtiles of 32 positions)
constexpr int TP    = 32;          // positions per subtile
constexpr int PITCH = 36;          // 9 x 16B rows: LDS.128-aligned, odd quad-bank stride
constexpr int TH1   = 192;         // 3 groups x 64 threads
constexpr int NREP  = 4;           // atomic accumulator replicas

// Replicated accumulators: [replica][item][mat][32*32]. Zero at module load;
// k_final re-zeroes after reading so every graph replay starts clean.
__device__ float g_acc[(size_t)NREP * NI * 3 * 1024];

// Physical row for logical channel c: spreads the 8-strided row sets used by
// the main loop across all 8 quad-banks (conflict-free LDS.128).
__device__ __forceinline__ int rowmap(int c) { return ((c & 3) << 3) | (c >> 2); }

__global__ __launch_bounds__(TH1) void k_partial(const float* __restrict__ S,
                                                 const float* __restrict__ T,
                                                 float* __restrict__ out) {
    __shared__ __align__(16) float sS[2][Cc * PITCH];
    __shared__ __align__(16) float sT[2][Cc * PITCH];
    __shared__ __align__(16) float ivS[2][TP];
    __shared__ __align__(16) float ivT[2][TP];

    const int n   = blockIdx.y;
    const int blk = blockIdx.x;
    const int tid = threadIdx.x;

    if (blk == 0 && n == 0 && tid == 0) *out = 0.f;   // graph edge orders this before k_final

    const float4* __restrict__ Sb4 = (const float4*)(S + (size_t)n * Cc * HW);
    const float4* __restrict__ Tb4 = (const float4*)(T + (size_t)n * Cc * HW);

    // Per-thread load slots: 256 float4-pairs per subtile; slots tid, tid+192
    const int p0 = blk * 2 * TP;
    const int c0 = tid >> 3,          q0 = tid & 7;
    const int v1 = tid + TH1;
    const int c1 = (v1 < 256) ? (v1 >> 3) : 0, q1 = (v1 < 256) ? (v1 & 7) : 0;
    const bool has1 = (v1 < 256);

    // ---- Prefetch subtile 0 ----
    float4 a0 = Sb4[(size_t)c0 * (HW / 4) + (p0 >> 2) + q0];
    float4 b0 = Tb4[(size_t)c0 * (HW / 4) + (p0 >> 2) + q0];
    float4 a1 = {}, b1 = {};
    if (has1) {
        a1 = Sb4[(size_t)c1 * (HW / 4) + (p0 >> 2) + q1];
        b1 = Tb4[(size_t)c1 * (HW / 4) + (p0 >> 2) + q1];
    }

    const int grp = tid >> 6;          // 0:A(T.T^t) 1:B(S.S^t) 2:M(S.T^t)
    const int lt  = tid & 63;
    const int ii  = lt >> 3;           // 0..7
    const int jj  = lt & 7;            // 0..7

    unsigned long long acc2[16];
#pragma unroll
    for (int k = 0; k < 16; ++k) acc2[k] = 0ull;

#pragma unroll
    for (int t = 0; t < 2; ++t) {
        // ---- Store current subtile to smem (row-permuted) ----
        *(float4*)&sS[t][rowmap(c0) * PITCH + 4 * q0] = a0;
        *(float4*)&sT[t][rowmap(c0) * PITCH + 4 * q0] = b0;
        if (has1) {
            *(float4*)&sS[t][rowmap(c1) * PITCH + 4 * q1] = a1;
            *(float4*)&sT[t][rowmap(c1) * PITCH + 4 * q1] = b1;
        }

        if (t == 0) {   // prefetch subtile 1 while subtile 0 is processed
            const int pn = p0 + TP;
            a0 = Sb4[(size_t)c0 * (HW / 4) + (pn >> 2) + q0];
            b0 = Tb4[(size_t)c0 * (HW / 4) + (pn >> 2) + q0];
            if (has1) {
                a1 = Sb4[(size_t)c1 * (HW / 4) + (pn >> 2) + q1];
                b1 = Tb4[(size_t)c1 * (HW / 4) + (pn >> 2) + q1];
            }
        }
        __syncthreads();

        // ---- Norms (4-way ILP chains): warp0 -> ivS, warp1 -> ivT ----
        if (tid < TP) {
            const int p = tid;
            float s0 = 0.f, s1 = 0.f, s2 = 0.f, s3 = 0.f;
#pragma unroll
            for (int r = 0; r < 8; ++r) {
                const float x0 = sS[t][(r     ) * PITCH + p];
                const float x1 = sS[t][(r +  8) * PITCH + p];
                const float x2 = sS[t][(r + 16) * PITCH + p];
                const float x3 = sS[t][(r + 24) * PITCH + p];
                s0 = fmaf(x0, x0, s0); s1 = fmaf(x1, x1, s1);
                s2 = fmaf(x2, x2, s2); s3 = fmaf(x3, x3, s3);
            }
            ivS[t][p] = 1.f / (sqrtf((s0 + s1) + (s2 + s3)) + 1e-8f);
        } else if (tid < 2 * TP) {
            const int p = tid - TP;
            float s0 = 0.f, s1 = 0.f, s2 = 0.f, s3 = 0.f;
#pragma unroll
            for (int r = 0; r < 8; ++r) {
                const float x0 = sT[t][(r     ) * PITCH + p];
                const float x1 = sT[t][(r +  8) * PITCH + p];
                const float x2 = sT[t][(r + 16) * PITCH + p];
                const float x3 = sT[t][(r + 24) * PITCH + p];
                s0 = fmaf(x0, x0, s0); s1 = fmaf(x1, x1, s1);
                s2 = fmaf(x2, x2, s2); s3 = fmaf(x3, x3, s3);
            }
            ivT[t][p] = 1.f / (sqrtf((s0 + s1) + (s2 + s3)) + 1e-8f);
        }
        __syncthreads();

        // ---- Normalize tiles in place (serves all three Grams correctly) ----
#pragma unroll
        for (int s = tid; s < 512; s += TH1) {
            const int half = s >> 8;            // 0: sS, 1: sT
            const int R = (s & 255) >> 3, q = s & 7;
            float* base = half ? sT[t] : sS[t];
            const float* iv = half ? ivT[t] : ivS[t];
            const float4 w = *(const float4*)&iv[4 * q];
            float4 v = *(float4*)&base[R * PITCH + 4 * q];
            v.x *= w.x; v.y *= w.y; v.z *= w.z; v.w *= w.w;
            *(float4*)&base[R * PITCH + 4 * q] = v;
        }
        __syncthreads();

        // ---- Gram accumulation, register double-buffered ----
        const float* __restrict__ Xi = (grp == 0) ? sT[t] : sS[t];
        const float* __restrict__ Xj = (grp == 1) ? sS[t] : sT[t];
        const float* xiB = Xi + ii * PITCH;
        const float* xjB = Xj + jj * PITCH;

        float4 xi4[4], xj4[4];
#pragma unroll
        for (int rr = 0; rr < 4; ++rr) xi4[rr] = *(const float4*)&xiB[(8 * rr) * PITCH];
#pragma unroll
        for (int qq = 0; qq < 4; ++qq) xj4[qq] = *(const float4*)&xjB[(8 * qq) * PITCH];

#pragma unroll
        for (int p = 0; p < TP; p += 4) {
            float4 cxi[4], cxj[4];
#pragma unroll
            for (int k = 0; k < 4; ++k) { cxi[k] = xi4[k]; cxj[k] = xj4[k]; }

            if (p + 4 < TP) {   // prefetch next step's operands (covers LDS latency)
#pragma unroll
                for (int rr = 0; rr < 4; ++rr)
                    xi4[rr] = *(const float4*)&xiB[(8 * rr) * PITCH + p + 4];
#pragma unroll
                for (int qq = 0; qq < 4; ++qq)
                    xj4[qq] = *(const float4*)&xjB[(8 * qq) * PITCH + p + 4];
            }

#pragma unroll
            for (int rr = 0; rr < 4; ++rr) {
                const unsigned long long xiL = *(const unsigned long long*)&cxi[rr].x;
                const unsigned long long xiH = *(const unsigned long long*)&cxi[rr].z;
#pragma unroll
                for (int qq = 0; qq < 4; ++qq) {
                    const unsigned long long xjL = *(const unsigned long long*)&cxj[qq].x;
                    const unsigned long long xjH = *(const unsigned long long*)&cxj[qq].z;
                    asm("fma.rn.f32x2 %0, %1, %2, %0;"
                        : "+l"(acc2[rr * 4 + qq]) : "l"(xiL), "l"(xjL));
                    asm("fma.rn.f32x2 %0, %1, %2, %0;"
                        : "+l"(acc2[rr * 4 + qq]) : "l"(xiH), "l"(xjH));
                }
            }
        }
        // No barrier needed: next iteration's STS targets the other buffer.
    }

    // ---- Fire-and-forget accumulation into replicated slot ----
    const int rep = blk & (NREP - 1);
    float* dst = g_acc + ((size_t)(rep * NI + n) * 3 + grp) * 1024;
#pragma unroll
    for (int rr = 0; rr < 4; ++rr)
#pragma unroll
        for (int qq = 0; qq < 4; ++qq) {
            const float2 v = *(const float2*)&acc2[rr * 4 + qq];
            atomicAdd(&dst[(4 * ii + rr) * 32 + 4 * jj + qq], v.x + v.y);
        }
}

// 48 blocks x 512 threads: exactly one thread per Gram element (8*3*1024).
// Coalesced replica loads, warp-shuffle reduce, one atomicAdd per block.
__global__ __launch_bounds__(512) void k_final(float* __restrict__ out) {
    const int t   = threadIdx.x;
    const int gid = blockIdx.x * 512 + t;             // 0..24575
    const int n   = gid / 3072;
    const int rem = gid % 3072;                       // mat*1024 + el
    const int mat = rem >> 10;

    float v = 0.f;
#pragma unroll
    for (int r = 0; r < NREP; ++r)
        v += g_acc[(size_t)(r * NI + n) * 3072 + rem];
#pragma unroll
    for (int r = 0; r < NREP; ++r)
        g_acc[(size_t)(r * NI + n) * 3072 + rem] = 0.f;

    float contrib = (mat == 2) ? -2.f * v * v : v * v;

#pragma unroll
    for (int off = 16; off > 0; off >>= 1)
        contrib += __shfl_down_sync(0xffffffffu, contrib, off);

    __shared__ float wsum[16];
    if ((t & 31) == 0) wsum[t >> 5] = contrib;
    __syncthreads();

    if (t < 32) {
        float s = (t < 16) ? wsum[t] : 0.f;
#pragma unroll
        for (int off = 8; off > 0; off >>= 1)
            s += __shfl_down_sync(0xffffffffu, s, off);
        // loss = total / (HW^2) / (B*L)
        if (t == 0) atomicAdd(out, s * (1.f / (16777216.f * 8.f)));
    }
}

extern "C" void kernel_launch(void* const* d_in, const int* in_sizes, int n_in,
                              void* d_out, int out_size) {
    const float* S = (const float*)d_in[0];
    const float* T = (const float*)d_in[1];
    (void)in_sizes; (void)n_in; (void)out_size;

    dim3 g1(BPI, NI);
    k_partial<<<g1, TH1>>>(S, T, (float*)d_out);
    k_final<<<48, 512>>>((float*)d_out);
}

// round 11
// speedup vs baseline: 1.9828x; 1.0086x over previous
#include <cuda_runtime.h>
#include <math.h>

// Shapes fixed by reference: [2,4,32,64,64]
constexpr int Cc    = 32;          // channels
constexpr int HW    = 4096;        // 64*64 positions
constexpr int NI    = 8;           // B*L items
constexpr int TPB   = 128;         // positions per block
constexpr int BPI   = 32;          // blocks per item
constexpr int PITCH = 132;         // 128 + 4: 16B-aligned rows, PITCH % 32 == 4
constexpr int TH1   = 192;         // 3 mats x 2 teams x 32 patches
constexpr int NREP  = 4;           // atomic accumulator replicas

// Replicated accumulators: [replica][item][mat][32*32]. Zero at module load;
// k_final re-zeroes after reading so every graph replay starts clean.
__device__ float g_acc[(size_t)NREP * NI * 3 * 1024];

// Physical row for logical channel c.  sigma(c) = ((c&3)<<3)|(c>>2).
// Guarantees conflict-free u64 LDS for both access patterns of the main loop:
//   xi rows {8*ii+rr}: sigma%8 = 2*ii + (rr>>2)  -> 4 distinct chunks/instr
//   xj rows {4*jj+qq}: sigma   = 8*qq + jj       -> 8 distinct chunks/instr
__device__ __forceinline__ int rowmap(int c) { return ((c & 3) << 3) | (c >> 2); }

__global__ __launch_bounds__(TH1, 2) void k_partial(const float* __restrict__ S,
                                                    const float* __restrict__ T,
                                                    float* __restrict__ out) {
    __shared__ __align__(16) float sS[Cc * PITCH];
    __shared__ __align__(16) float sT[Cc * PITCH];
    __shared__ __align__(16) float ivS[TPB];
    __shared__ __align__(16) float ivT[TPB];

    const int n   = blockIdx.y;
    const int blk = blockIdx.x;
    const int tid = threadIdx.x;
    const int p0  = blk * TPB;

    if (blk == 0 && n == 0 && tid == 0) *out = 0.f;   // graph edge orders before k_final

    const float4* __restrict__ Sb4 = (const float4*)(S + (size_t)n * Cc * HW);
    const float4* __restrict__ Tb4 = (const float4*)(T + (size_t)n * Cc * HW);

    // ---- Load tile [2 x 32 x 128] as float4 (coalesced), rows permuted ----
    for (int s = tid; s < 2 * Cc * (TPB / 4); s += TH1) {
        const int tensor = s >> 10;          // 0: S, 1: T
        const int c = (s >> 5) & 31;
        const int q = s & 31;                // float4 index (positions 4q..4q+3)
        const float4 v = tensor ? Tb4[(size_t)c * (HW / 4) + (p0 >> 2) + q]
                                : Sb4[(size_t)c * (HW / 4) + (p0 >> 2) + q];
        float* dstA = tensor ? sT : sS;
        *(float4*)&dstA[rowmap(c) * PITCH + 4 * q] = v;
    }
    __syncthreads();

    // ---- Per-position inverse norms (4-way ILP; 256 norms / 192 threads) ----
    for (int idx = tid; idx < 2 * TPB; idx += TH1) {
        const int half = idx >> 7;           // 0: S, 1: T
        const int p = idx & 127;
        const float* arr = half ? sT : sS;
        float s0 = 0.f, s1 = 0.f, s2 = 0.f, s3 = 0.f;
#pragma unroll
        for (int r = 0; r < 8; ++r) {
            const float x0 = arr[(r     ) * PITCH + p];
            const float x1 = arr[(r +  8) * PITCH + p];
            const float x2 = arr[(r + 16) * PITCH + p];
            const float x3 = arr[(r + 24) * PITCH + p];
            s0 = fmaf(x0, x0, s0); s1 = fmaf(x1, x1, s1);
            s2 = fmaf(x2, x2, s2); s3 = fmaf(x3, x3, s3);
        }
        const float iv = 1.f / (sqrtf((s0 + s1) + (s2 + s3)) + 1e-8f);
        (half ? ivT : ivS)[p] = iv;
    }
    __syncthreads();

    // ---- Normalize tiles in place (float4) ----
    for (int s = tid; s < 2 * Cc * (TPB / 4); s += TH1) {
        const int tensor = s >> 10;
        const int r = (s >> 5) & 31;         // physical row
        const int q = s & 31;
        float* arr = tensor ? sT : sS;
        const float* iv = tensor ? ivT : ivS;
        const float4 w = *(const float4*)&iv[4 * q];
        float4 v = *(float4*)&arr[r * PITCH + 4 * q];
        v.x *= w.x; v.y *= w.y; v.z *= w.z; v.w *= w.w;
        *(float4*)&arr[r * PITCH + 4 * q] = v;
    }
    __syncthreads();

    // ---- Gram accumulation: 8x4 patches, f32x2 over position pairs ----
    // tid = mat*64 + team*32 + patch;  patch: ii = patch>>3 (row block of 8),
    // jj = patch&7 (col block of 4).  Team k handles pairs {2m + k}, m=0..31.
    const int mat   = tid >> 6;          // 0:A(T.T^t) 1:B(S.S^t) 2:M(S.T^t)
    const int team  = (tid >> 5) & 1;
    const int patch = tid & 31;
    const int ii    = patch >> 3;        // 0..3
    const int jj    = patch & 7;         // 0..7

    const float* __restrict__ Xi = (mat == 0) ? sT : sS;
    const float* __restrict__ Xj = (mat == 1) ? sS : sT;
    // sigma(8*ii+rr) = (8*(rr&3) + (rr>>2)) + 2*ii ; sigma(4*jj+qq) = 8*qq + jj
    const float* xiB = Xi + 2 * ii * PITCH + 2 * team;
    const float* xjB = Xj + jj * PITCH     + 2 * team;

    unsigned long long acc2[32];
#pragma unroll
    for (int k = 0; k < 32; ++k) acc2[k] = 0ull;

#pragma unroll 4
    for (int m = 0; m < 32; ++m) {
        const int off = 4 * m;           // + 2*team folded into base pointers

        unsigned long long xj2[4];
#pragma unroll
        for (int qq = 0; qq < 4; ++qq)
            xj2[qq] = *(const unsigned long long*)&xjB[(8 * qq) * PITCH + off];

        unsigned long long xi2[8];
#pragma unroll
        for (int rr = 0; rr < 8; ++rr)
            xi2[rr] = *(const unsigned long long*)&xiB[(8 * (rr & 3) + (rr >> 2)) * PITCH + off];

#pragma unroll
        for (int rr = 0; rr < 8; ++rr)
#pragma unroll
            for (int qq = 0; qq < 4; ++qq)
                asm("fma.rn.f32x2 %0, %1, %2, %0;"
                    : "+l"(acc2[rr * 4 + qq]) : "l"(xi2[rr]), "l"(xj2[qq]));
    }

    // ---- Fire-and-forget accumulation; replica spreads contenders ----
    const int rep = blk & (NREP - 1);
    float* dst = g_acc + ((size_t)(rep * NI + n) * 3 + mat) * 1024;
#pragma unroll
    for (int rr = 0; rr < 8; ++rr)
#pragma unroll
        for (int qq = 0; qq < 4; ++qq) {
            const float2 v = *(const float2*)&acc2[rr * 4 + qq];
            atomicAdd(&dst[(8 * ii + rr) * 32 + 4 * jj + qq], v.x + v.y);
        }
}

// 48 blocks x 512 threads: exactly one thread per Gram element (8*3*1024).
// Coalesced replica loads, warp-shuffle reduce, one atomicAdd per block.
__global__ __launch_bounds__(512) void k_final(float* __restrict__ out) {
    const int t   = threadIdx.x;
    const int gid = blockIdx.x * 512 + t;             // 0..24575
    const int n   = gid / 3072;
    const int rem = gid % 3072;                       // mat*1024 + el
    const int mat = rem >> 10;

    float v = 0.f;
#pragma unroll
    for (int r = 0; r < NREP; ++r)
        v += g_acc[(size_t)(r * NI + n) * 3072 + rem];
#pragma unroll
    for (int r = 0; r < NREP; ++r)
        g_acc[(size_t)(r * NI + n) * 3072 + rem] = 0.f;

    float contrib = (mat == 2) ? -2.f * v * v : v * v;

#pragma unroll
    for (int off = 16; off > 0; off >>= 1)
        contrib += __shfl_down_sync(0xffffffffu, contrib, off);

    __shared__ float wsum[16];
    if ((t & 31) == 0) wsum[t >> 5] = contrib;
    __syncthreads();

    if (t < 32) {
        float s = (t < 16) ? wsum[t] : 0.f;
#pragma unroll
        for (int off = 8; off > 0; off >>= 1)
            s += __shfl_down_sync(0xffffffffu, s, off);
        // loss = total / (HW^2) / (B*L)
        if (t == 0) atomicAdd(out, s * (1.f / (16777216.f * 8.f)));
    }
}

extern "C" void kernel_launch(void* const* d_in, const int* in_sizes, int n_in,
                              void* d_out, int out_size) {
    const float* S = (const float*)d_in[0];
    const float* T = (const float*)d_in[1];
    (void)in_sizes; (void)n_in; (void)out_size;

    dim3 g1(BPI, NI);
    k_partial<<<g1, TH1>>>(S, T, (float*)d_out);
    k_final<<<48, 512>>>((float*)d_out);
}